// round 1
// baseline (speedup 1.0000x reference)
#include <cuda_runtime.h>
#include <math.h>

// Problem constants (shape fixed by reference: [4,1,128,256,256] fp32)
#define IMG_W 256
#define IMG_H 256
#define NSLICES 512            // B * D = 4 * 128
#define ROWS 16                // output rows per block
#define BANDS (IMG_H / ROWS)   // 16 blocks per slice vertically
#define NBLOCKS (NSLICES * BANDS)  // 8192
#define TILE_H (ROWS + 2)      // 18 (with top/bottom halo)
#define TILE_W (IMG_W + 2)     // 258 (with left/right halo)
#define N_TOTAL (4.0 * 128.0 * 256.0 * 256.0)

// Scratch for deterministic two-stage reduction (no device allocation allowed)
__device__ float g_partials[NBLOCKS];

// ---------------------------------------------------------------------------
// Kernel 1: per-band Sobel magnitude |diff| partial sums.
// One block = 256 threads = one column each, covering ROWS output rows of one
// (b,d) slice. Separable Sobel via rolling row-sums: per output pixel we do
// only 3 shared loads per image (the new bottom row l,m,r), reusing h1/h2
// row aggregates vertically in registers.
//   h1 = r - l          -> ex = h1[y-1] + 2*h1[y] + h1[y+1]
//   h2 = l + 2m + r     -> ey = h2[y+1] - h2[y-1]
// (cross-correlation per XLA conv; sign is irrelevant under the magnitude)
// ---------------------------------------------------------------------------
__global__ __launch_bounds__(256)
void sobel_loss_partial_kernel(const float* __restrict__ pred,
                               const float* __restrict__ target)
{
    __shared__ float sp[TILE_H][TILE_W];
    __shared__ float st[TILE_H][TILE_W];
    __shared__ float warp_sums[8];

    const int band  = blockIdx.x;     // 0..BANDS-1
    const int slice = blockIdx.y;     // 0..NSLICES-1
    const int tid   = threadIdx.x;    // 0..255
    const int r0    = band * ROWS;

    const size_t base = (size_t)slice * (IMG_H * IMG_W);
    const float* __restrict__ P = pred + base;
    const float* __restrict__ T = target + base;

    // ---- Cooperative halo-tile load (zero padding at image borders) ----
    #pragma unroll 4
    for (int idx = tid; idx < TILE_H * TILE_W; idx += 256) {
        const int row = idx / TILE_W;
        const int col = idx - row * TILE_W;
        const int gy  = r0 - 1 + row;
        const int gx  = col - 1;
        float vp = 0.0f, vt = 0.0f;
        if (gy >= 0 && gy < IMG_H && gx >= 0 && gx < IMG_W) {
            const int o = gy * IMG_W + gx;
            vp = __ldg(&P[o]);
            vt = __ldg(&T[o]);
        }
        sp[row][col] = vp;
        st[row][col] = vt;
    }
    __syncthreads();

    // ---- Column walk with rolling separable row-aggregates ----
    const int c = tid + 1;  // shared column for image x == tid

    float ph1_0, ph1_1, ph2_0, ph2_1;   // pred rolling rows y-1, y
    float th1_0, th1_1, th2_0, th2_1;   // target rolling rows
    {
        float l = sp[0][c - 1], m = sp[0][c], r = sp[0][c + 1];
        ph1_0 = r - l; ph2_0 = l + 2.0f * m + r;
        l = st[0][c - 1]; m = st[0][c]; r = st[0][c + 1];
        th1_0 = r - l; th2_0 = l + 2.0f * m + r;

        l = sp[1][c - 1]; m = sp[1][c]; r = sp[1][c + 1];
        ph1_1 = r - l; ph2_1 = l + 2.0f * m + r;
        l = st[1][c - 1]; m = st[1][c]; r = st[1][c + 1];
        th1_1 = r - l; th2_1 = l + 2.0f * m + r;
    }

    float acc = 0.0f;
    #pragma unroll
    for (int rr = 0; rr < ROWS; rr++) {
        const int sr = rr + 2;  // new bottom row of the 3-row window

        float l = sp[sr][c - 1], m = sp[sr][c], r = sp[sr][c + 1];
        const float ph1_2 = r - l;
        const float ph2_2 = l + 2.0f * m + r;
        l = st[sr][c - 1]; m = st[sr][c]; r = st[sr][c + 1];
        const float th1_2 = r - l;
        const float th2_2 = l + 2.0f * m + r;

        float ex = ph1_0 + 2.0f * ph1_1 + ph1_2;
        float ey = ph2_2 - ph2_0;
        const float magp = sqrtf(fmaf(ex, ex, fmaf(ey, ey, 1e-8f)));

        ex = th1_0 + 2.0f * th1_1 + th1_2;
        ey = th2_2 - th2_0;
        const float magt = sqrtf(fmaf(ex, ex, fmaf(ey, ey, 1e-8f)));

        acc += fabsf(magp - magt);

        ph1_0 = ph1_1; ph1_1 = ph1_2;
        ph2_0 = ph2_1; ph2_1 = ph2_2;
        th1_0 = th1_1; th1_1 = th1_2;
        th2_0 = th2_1; th2_1 = th2_2;
    }

    // ---- Deterministic block reduction: warp shuffle tree + serial 8-sum ----
    #pragma unroll
    for (int off = 16; off > 0; off >>= 1)
        acc += __shfl_down_sync(0xffffffffu, acc, off);

    const int wid  = tid >> 5;
    const int lane = tid & 31;
    if (lane == 0) warp_sums[wid] = acc;
    __syncthreads();

    if (tid == 0) {
        float s = 0.0f;
        #pragma unroll
        for (int i = 0; i < 8; i++) s += warp_sums[i];
        g_partials[slice * BANDS + band] = s;
    }
}

// ---------------------------------------------------------------------------
// Kernel 2: deterministic final reduction of 8192 partials -> mean scalar.
// Fixed strided per-thread accumulation in double, then fixed shared tree.
// ---------------------------------------------------------------------------
__global__ __launch_bounds__(256)
void final_reduce_kernel(float* __restrict__ out)
{
    __shared__ double sred[256];
    const int tid = threadIdx.x;

    double s = 0.0;
    #pragma unroll 8
    for (int i = tid; i < NBLOCKS; i += 256)
        s += (double)g_partials[i];
    sred[tid] = s;
    __syncthreads();

    #pragma unroll
    for (int off = 128; off > 0; off >>= 1) {
        if (tid < off) sred[tid] += sred[tid + off];
        __syncthreads();
    }

    if (tid == 0)
        out[0] = (float)(sred[0] / N_TOTAL);
}

extern "C" void kernel_launch(void* const* d_in, const int* in_sizes, int n_in,
                              void* d_out, int out_size)
{
    (void)in_sizes; (void)n_in; (void)out_size;
    const float* pred   = (const float*)d_in[0];
    const float* target = (const float*)d_in[1];
    float* out = (float*)d_out;

    dim3 grid(BANDS, NSLICES);   // 16 x 512 = 8192 blocks
    sobel_loss_partial_kernel<<<grid, 256>>>(pred, target);
    final_reduce_kernel<<<1, 256>>>(out);
}